// round 7
// baseline (speedup 1.0000x reference)
#include <cuda_runtime.h>
#include <cstdint>
#include <cstddef>

#define TOKENS (2*128*128)
typedef unsigned long long ull;

// ---------------- scratch ---------------------------------------------------
__device__ float g_feat[TOKENS*60];
__device__ float g_qkv [TOKENS*180];
__device__ float g_attn[TOKENS*60];

// ---------------- packed fp32 helpers (sm_103a f32x2) -----------------------
__device__ __forceinline__ ull fma2(ull a, ull b, ull c){
  ull d; asm("fma.rn.f32x2 %0,%1,%2,%3;" : "=l"(d) : "l"(a), "l"(b), "l"(c)); return d;
}
__device__ __forceinline__ ull add2(ull a, ull b){
  ull d; asm("add.rn.f32x2 %0,%1,%2;" : "=l"(d) : "l"(a), "l"(b)); return d;
}
__device__ __forceinline__ ull pk2(float lo, float hi){
  ull d; asm("mov.b64 %0,{%1,%2};" : "=l"(d) : "f"(lo), "f"(hi)); return d;
}
__device__ __forceinline__ ull pkdup(float v){ return pk2(v, v); }
__device__ __forceinline__ void unpk2f(float& lo, float& hi, ull v){
  asm("mov.b64 {%0,%1},%2;" : "=f"(lo), "=f"(hi) : "l"(v));
}
__device__ __forceinline__ void unpk2u(unsigned& lo, unsigned& hi, ull v){
  asm("mov.b64 {%0,%1},%2;" : "=r"(lo), "=r"(hi) : "l"(v));
}

// packed 2^s for two lanes; s already in log2 domain, s > -126 guaranteed.
__device__ __forceinline__ ull pexp2(ull s, ull kMAGIC, ull kNEG1,
                                     ull c5, ull c4, ull c3, ull c2, ull c1, ull c0){
  ull kf = add2(s, kMAGIC);           // round-to-int via magic
  ull fi = fma2(kMAGIC, kNEG1, kf);   // fi = kf - magic (integer part, exact)
  ull f  = fma2(fi, kNEG1, s);        // f = s - fi, in [-0.5, 0.5]
  ull p  = fma2(c5, f, c4);
  p = fma2(p, f, c3); p = fma2(p, f, c2); p = fma2(p, f, c1); p = fma2(p, f, c0);
  unsigned klo, khi, plo, phi;
  unpk2u(klo, khi, kf);               // bits(12582912 + i) = 0x4B400000 + i
  unpk2u(plo, phi, p);
  plo += (klo << 23);                 // (0x4B400000<<23) == 0 mod 2^32
  phi += (khi << 23);
  ull r; asm("mov.b64 %0,{%1,%2};" : "=l"(r) : "r"(plo), "r"(phi)); return r;
}

// ---------------- scalar FFMA-only exp / rcp (swish epilogue) ---------------
__device__ __forceinline__ float fexp(float x){
  x = fminf(fmaxf(x, -87.0f), 87.0f);
  float t  = x * 1.4426950408889634f;
  float kf = t + 12582912.0f;
  float i  = kf - 12582912.0f;
  float f  = t - i;
  float p  = 1.3333558e-3f;
  p = fmaf(p, f, 9.6181291e-3f);
  p = fmaf(p, f, 5.5504109e-2f);
  p = fmaf(p, f, 2.4022651e-1f);
  p = fmaf(p, f, 6.9314718e-1f);
  p = fmaf(p, f, 1.0f);
  int e = (int)i;
  return p * __int_as_float((e + 127) << 23);
}
__device__ __forceinline__ float frcp_nr(float y){
  float r = __int_as_float(0x7EF311C3u - __float_as_int(y));
  r = r * (2.0f - y * r);
  r = r * (2.0f - y * r);
  return r;
}

// ---------------- first conv ------------------------------------------------
__global__ __launch_bounds__(256) void conv_in_kernel(
    const float* __restrict__ x, const float* __restrict__ w,
    const float* __restrict__ b, float* __restrict__ feat)
{
  int idx = blockIdx.x*256 + threadIdx.x;
  if (idx >= TOKENS*60) return;
  int co = idx % 60;
  int t  = idx / 60;
  int wq = t & 127;
  int hq = (t >> 7) & 127;
  int bq = t >> 14;
  float s = b[co];
  #pragma unroll
  for (int kh = 0; kh < 3; kh++){
    int hh = hq + kh - 1;
    if ((unsigned)hh > 127u) continue;
    #pragma unroll
    for (int kw = 0; kw < 3; kw++){
      int wwq = wq + kw - 1;
      if ((unsigned)wwq > 127u) continue;
      const float* xp = x + (size_t)((bq*3)*128 + hh)*128 + wwq;
      #pragma unroll
      for (int ci = 0; ci < 3; ci++)
        s = fmaf(xp[(size_t)ci*128*128], w[((co*3+ci)*3+kh)*3+kw], s);
    }
  }
  feat[idx] = s;
}

// ---------------- GEMM: 128M x 60N, 480 threads, 4x4 tile, f32x2 -----------
// Xs transposed [k][m] pad-130 (8B-aligned m-pair loads).  Acc packed over
// m-pairs; b scalars duplicated.
template<int K, bool DOLN, bool RESID>
__global__ __launch_bounds__(480) void gemm_kernel(
    const float* __restrict__ X, const float* __restrict__ W,
    const float* __restrict__ bias,
    const float* __restrict__ lng, const float* __restrict__ lnb,
    float* __restrict__ Out, int Nfull)
{
  static_assert(!(DOLN && K != 60), "LN fusion only for K=60");
  __shared__ float Xs[60][130];
  __shared__ float Ws[60][60];
  __shared__ float lg[60], lb[60];
  const int m0  = blockIdx.x * 128;
  const int n0  = blockIdx.y * 60;
  const int tid = threadIdx.x;
  const int tx  = tid % 15;        // n group (4 cols)
  const int ty  = tid / 15;        // m group (4 rows), 0..31

  if (DOLN && tid < 60){ lg[tid] = lng[tid]; lb[tid] = lnb[tid]; }

  ull acc[2][4];
  #pragma unroll
  for (int p = 0; p < 2; p++)
    #pragma unroll
    for (int j = 0; j < 4; j++) acc[p][j] = 0ull;

  for (int k0 = 0; k0 < K; k0 += 60){
    #pragma unroll
    for (int idx = tid; idx < 128*60; idx += 480){
      int m = idx / 60, k = idx - m*60;
      Xs[k][m] = X[(size_t)(m0+m)*K + k0 + k];
    }
    #pragma unroll
    for (int idx = tid; idx < 60*60; idx += 480){
      int k = idx / 60, n = idx - k*60;
      Ws[k][n] = W[(size_t)(k0+k)*Nfull + n0 + n];
    }
    __syncthreads();
    if (DOLN){
      if (tid < 128){
        float mu = 0.f;
        #pragma unroll
        for (int c = 0; c < 60; c++) mu += Xs[c][tid];
        mu *= (1.0f/60.0f);
        float var = 0.f;
        #pragma unroll
        for (int c = 0; c < 60; c++){ float d = Xs[c][tid]-mu; var = fmaf(d,d,var); }
        float rs = rsqrtf(var*(1.0f/60.0f) + 1e-5f);
        #pragma unroll
        for (int c = 0; c < 60; c++)
          Xs[c][tid] = (Xs[c][tid]-mu)*rs*lg[c] + lb[c];
      }
      __syncthreads();
    }
    #pragma unroll 10
    for (int k = 0; k < 60; k++){
      const ull* ap = reinterpret_cast<const ull*>(&Xs[k][ty*4]);
      ull a01 = ap[0];
      ull a23 = ap[1];
      float4 b4 = *reinterpret_cast<const float4*>(&Ws[k][tx*4]);
      ull bx = pkdup(b4.x), by = pkdup(b4.y), bz = pkdup(b4.z), bw = pkdup(b4.w);
      acc[0][0] = fma2(a01, bx, acc[0][0]);
      acc[0][1] = fma2(a01, by, acc[0][1]);
      acc[0][2] = fma2(a01, bz, acc[0][2]);
      acc[0][3] = fma2(a01, bw, acc[0][3]);
      acc[1][0] = fma2(a23, bx, acc[1][0]);
      acc[1][1] = fma2(a23, by, acc[1][1]);
      acc[1][2] = fma2(a23, bz, acc[1][2]);
      acc[1][3] = fma2(a23, bw, acc[1][3]);
    }
    __syncthreads();
  }

  // unpack: acc[p][j] = (row ty*4+2p, row ty*4+2p+1) for col tx*4+j
  float r[4][4];
  #pragma unroll
  for (int p = 0; p < 2; p++)
    #pragma unroll
    for (int j = 0; j < 4; j++)
      unpk2f(r[2*p][j], r[2*p+1][j], acc[p][j]);

  float4 bb = *reinterpret_cast<const float4*>(&bias[n0 + tx*4]);
  #pragma unroll
  for (int i = 0; i < 4; i++){
    size_t o = (size_t)(m0 + ty*4 + i) * Nfull + n0 + tx*4;
    float v0 = r[i][0] + bb.x;
    float v1 = r[i][1] + bb.y;
    float v2 = r[i][2] + bb.z;
    float v3 = r[i][3] + bb.w;
    if (RESID){
      float4 old = *reinterpret_cast<const float4*>(&Out[o]);
      v0 += old.x; v1 += old.y; v2 += old.z; v3 += old.w;
    }
    *reinterpret_cast<float4*>(&Out[o]) = make_float4(v0, v1, v2, v3);
  }
}

// ---------------- fused MLP: feat += swish(LN2(feat)@W1+b1)@W2+b2 ----------
// 480 threads, f32x2.  Stage A: 4m x 8n tile (acc packed over n-pairs,
// b-pairs free from 16B smem loads).  Stage B: 4m x 4n.
#define FMLP_SMEM_BYTES (22680*4)
__global__ __launch_bounds__(480) void fused_mlp_kernel(
    float* __restrict__ feat,
    const float* __restrict__ W1, const float* __restrict__ b1,
    const float* __restrict__ W2, const float* __restrict__ b2,
    const float* __restrict__ lng, const float* __restrict__ lnb)
{
  extern __shared__ float pool[];
  float* Xs  = pool;           // [60][129]   7740 floats
  float* Ws1 = pool + 7740;    // [60][120]   7200 floats
  float* hs  = pool;           // [120][129] 15480 floats (union after stage A)
  float* Ws2 = pool + 15480;   // [120][60]   7200 floats
  __shared__ float lg[60], lb[60];

  const int m0  = blockIdx.x * 128;
  const int tid = threadIdx.x;
  const int tx  = tid % 15;    // n-group
  const int ty  = tid / 15;    // m-group, 0..31 (4 rows each)

  if (tid < 60){ lg[tid] = lng[tid]; lb[tid] = lnb[tid]; }

  #pragma unroll
  for (int idx = tid; idx < 128*60; idx += 480){
    int m = idx / 60, k = idx - m*60;
    Xs[k*129 + m] = feat[(size_t)(m0+m)*60 + k];
  }
  #pragma unroll
  for (int idx = tid; idx < 60*120; idx += 480) Ws1[idx] = W1[idx];
  #pragma unroll
  for (int idx = tid; idx < 120*60; idx += 480) Ws2[idx] = W2[idx];
  __syncthreads();

  if (tid < 128){
    float mu = 0.f;
    #pragma unroll
    for (int c = 0; c < 60; c++) mu += Xs[c*129 + tid];
    mu *= (1.0f/60.0f);
    float var = 0.f;
    #pragma unroll
    for (int c = 0; c < 60; c++){ float d = Xs[c*129 + tid]-mu; var = fmaf(d,d,var); }
    float rs = rsqrtf(var*(1.0f/60.0f) + 1e-5f);
    #pragma unroll
    for (int c = 0; c < 60; c++)
      Xs[c*129 + tid] = (Xs[c*129 + tid]-mu)*rs*lg[c] + lb[c];
  }
  __syncthreads();

  // stage A: h[4m][8n], acc packed over n-pairs (4 pairs)
  ull accA[4][4];
  #pragma unroll
  for (int i = 0; i < 4; i++)
    #pragma unroll
    for (int j = 0; j < 4; j++) accA[i][j] = 0ull;

  #pragma unroll 6
  for (int k = 0; k < 60; k++){
    const float* xr = &Xs[k*129 + ty*4];
    ull a0 = pkdup(xr[0]), a1 = pkdup(xr[1]), a2 = pkdup(xr[2]), a3 = pkdup(xr[3]);
    const ulonglong2* bp = reinterpret_cast<const ulonglong2*>(&Ws1[k*120 + tx*8]);
    ulonglong2 bb0 = bp[0];   // n-pairs (n0,n1),(n2,n3)
    ulonglong2 bb1 = bp[1];   // (n4,n5),(n6,n7)
    accA[0][0] = fma2(a0, bb0.x, accA[0][0]);
    accA[0][1] = fma2(a0, bb0.y, accA[0][1]);
    accA[0][2] = fma2(a0, bb1.x, accA[0][2]);
    accA[0][3] = fma2(a0, bb1.y, accA[0][3]);
    accA[1][0] = fma2(a1, bb0.x, accA[1][0]);
    accA[1][1] = fma2(a1, bb0.y, accA[1][1]);
    accA[1][2] = fma2(a1, bb1.x, accA[1][2]);
    accA[1][3] = fma2(a1, bb1.y, accA[1][3]);
    accA[2][0] = fma2(a2, bb0.x, accA[2][0]);
    accA[2][1] = fma2(a2, bb0.y, accA[2][1]);
    accA[2][2] = fma2(a2, bb1.x, accA[2][2]);
    accA[2][3] = fma2(a2, bb1.y, accA[2][3]);
    accA[3][0] = fma2(a3, bb0.x, accA[3][0]);
    accA[3][1] = fma2(a3, bb0.y, accA[3][1]);
    accA[3][2] = fma2(a3, bb1.x, accA[3][2]);
    accA[3][3] = fma2(a3, bb1.y, accA[3][3]);
  }

  // bias + swish (scalar), stash to registers
  float hv[4][8];
  {
    const float* bp1 = &b1[tx*8];
    #pragma unroll
    for (int i = 0; i < 4; i++)
      #pragma unroll
      for (int j = 0; j < 4; j++){
        float lo, hi; unpk2f(lo, hi, accA[i][j]);
        float v0 = lo + bp1[2*j], v1 = hi + bp1[2*j+1];
        hv[i][2*j]   = v0 * frcp_nr(1.0f + fexp(-v0));
        hv[i][2*j+1] = v1 * frcp_nr(1.0f + fexp(-v1));
      }
  }
  __syncthreads();   // done reading Xs/Ws1 before hs overwrite

  // stage hidden transposed: hs[n][m]
  #pragma unroll
  for (int j = 0; j < 8; j++)
    #pragma unroll
    for (int i = 0; i < 4; i++)
      hs[(tx*8 + j)*129 + ty*4 + i] = hv[i][j];
  __syncthreads();

  // stage B: out[4m][4n], k = 120
  ull accB[4][2];
  #pragma unroll
  for (int i = 0; i < 4; i++){ accB[i][0] = 0ull; accB[i][1] = 0ull; }

  #pragma unroll 6
  for (int k = 0; k < 120; k++){
    const float* hr = &hs[k*129 + ty*4];
    ull a0 = pkdup(hr[0]), a1 = pkdup(hr[1]), a2 = pkdup(hr[2]), a3 = pkdup(hr[3]);
    ulonglong2 bb = *reinterpret_cast<const ulonglong2*>(&Ws2[k*60 + tx*4]);
    accB[0][0] = fma2(a0, bb.x, accB[0][0]);
    accB[0][1] = fma2(a0, bb.y, accB[0][1]);
    accB[1][0] = fma2(a1, bb.x, accB[1][0]);
    accB[1][1] = fma2(a1, bb.y, accB[1][1]);
    accB[2][0] = fma2(a2, bb.x, accB[2][0]);
    accB[2][1] = fma2(a2, bb.y, accB[2][1]);
    accB[3][0] = fma2(a3, bb.x, accB[3][0]);
    accB[3][1] = fma2(a3, bb.y, accB[3][1]);
  }

  float4 bb2 = *reinterpret_cast<const float4*>(&b2[tx*4]);
  #pragma unroll
  for (int i = 0; i < 4; i++){
    float n0v, n1v, n2v, n3v;
    unpk2f(n0v, n1v, accB[i][0]);
    unpk2f(n2v, n3v, accB[i][1]);
    size_t o = (size_t)(m0 + ty*4 + i) * 60 + tx*4;
    float4 old = *reinterpret_cast<const float4*>(&feat[o]);
    *reinterpret_cast<float4*>(&feat[o]) = make_float4(
        old.x + n0v + bb2.x, old.y + n1v + bb2.y,
        old.z + n2v + bb2.z, old.w + n3v + bb2.w);
  }
}

// ---------------- windowed attention: f32x2, no-max softmax, j-quads -------
// K/V stored transposed in smem so 4 consecutive keys load as one LDS.128
// broadcast.  q pre-scaled by hd^-0.5 * log2(e); exp done in log2 domain.
template<int MASKED>
__global__ __launch_bounds__(256) void attn_kernel(
    const float* __restrict__ qkv, float* __restrict__ out,
    int wh, int ww, int sh, int sw)
{
  __shared__ float ksT[20][256];
  __shared__ float vsT[20][256];
  __shared__ int   rid[256];
  const int win  = blockIdx.x;
  const int head = blockIdx.y;
  const int nWc = 128 / ww;
  const int nHc = 128 / wh;
  const int b   = win / (nHc*nWc);
  const int rem = win % (nHc*nWc);
  const int ih  = rem / nWc, iw = rem % nWc;
  const int n   = threadIdx.x;
  const int r   = n / ww, col = n % ww;
  const int h   = ih*wh + r, w = iw*ww + col;
  const int gh  = (h + sh) & 127, gw = (w + sw) & 127;
  const int gidx = (b*128 + gh)*128 + gw;
  const float4* bp4 = reinterpret_cast<const float4*>(qkv + (size_t)gidx*180 + head*20);

  const float qs = 0.223606797749979f * 1.4426950408889634f;  // hd^-0.5 * log2e
  ull qd2[20];
  #pragma unroll
  for (int d4 = 0; d4 < 5; d4++){
    float4 qv = bp4[d4];
    float4 kv = bp4[15+d4];
    float4 vv = bp4[30+d4];
    qd2[4*d4+0] = pkdup(qv.x*qs);
    qd2[4*d4+1] = pkdup(qv.y*qs);
    qd2[4*d4+2] = pkdup(qv.z*qs);
    qd2[4*d4+3] = pkdup(qv.w*qs);
    ksT[4*d4+0][n] = kv.x; ksT[4*d4+1][n] = kv.y;
    ksT[4*d4+2][n] = kv.z; ksT[4*d4+3][n] = kv.w;
    vsT[4*d4+0][n] = vv.x; vsT[4*d4+1][n] = vv.y;
    vsT[4*d4+2][n] = vv.z; vsT[4*d4+3][n] = vv.w;
  }
  int rh = (h < 128-wh) ? 0 : ((h < 128-sh) ? 1 : 2);
  int rw = (w < 128-ww) ? 0 : ((w < 128-sw) ? 1 : 2);
  rid[n] = rh*3 + rw;
  __syncthreads();

  // packed exp constants (log2 domain)
  const ull kMAGIC = pkdup(12582912.0f);
  const ull kNEG1  = pkdup(-1.0f);
  const ull c5 = pkdup(1.3333558e-3f);
  const ull c4 = pkdup(9.6181291e-3f);
  const ull c3 = pkdup(5.5504109e-2f);
  const ull c2 = pkdup(2.4022651e-1f);
  const ull c1 = pkdup(6.9314718e-1f);
  const ull c0 = pkdup(1.0f);

  const int myrid = rid[n];
  ull l2 = 0ull;
  ull accP[20];
  #pragma unroll
  for (int d = 0; d < 20; d++) accP[d] = 0ull;

  for (int jq = 0; jq < 64; jq++){
    ull s01, s23;
    if (MASKED){
      int4 rq = *reinterpret_cast<const int4*>(&rid[jq*4]);
      // -110 in log2 domain: 2^-110 ~ 0, and stays > -126 (no exponent wrap)
      s01 = pk2((rq.x == myrid) ? 0.f : -110.f, (rq.y == myrid) ? 0.f : -110.f);
      s23 = pk2((rq.z == myrid) ? 0.f : -110.f, (rq.w == myrid) ? 0.f : -110.f);
    } else {
      s01 = 0ull; s23 = 0ull;
    }
    #pragma unroll
    for (int d = 0; d < 20; d++){
      ulonglong2 kk = *reinterpret_cast<const ulonglong2*>(&ksT[d][jq*4]);
      s01 = fma2(qd2[d], kk.x, s01);
      s23 = fma2(qd2[d], kk.y, s23);
    }
    ull p01 = pexp2(s01, kMAGIC, kNEG1, c5, c4, c3, c2, c1, c0);
    ull p23 = pexp2(s23, kMAGIC, kNEG1, c5, c4, c3, c2, c1, c0);
    l2 = add2(l2, p01);
    l2 = add2(l2, p23);
    #pragma unroll
    for (int d = 0; d < 20; d++){
      ulonglong2 vv = *reinterpret_cast<const ulonglong2*>(&vsT[d][jq*4]);
      accP[d] = fma2(p01, vv.x, accP[d]);
      accP[d] = fma2(p23, vv.y, accP[d]);
    }
  }

  float llo, lhi; unpk2f(llo, lhi, l2);
  float inv = 1.0f / (llo + lhi);
  float* op = out + (size_t)gidx*60 + head*20;
  #pragma unroll
  for (int d4 = 0; d4 < 5; d4++){
    float o0l, o0h, o1l, o1h, o2l, o2h, o3l, o3h;
    unpk2f(o0l, o0h, accP[4*d4+0]);
    unpk2f(o1l, o1h, accP[4*d4+1]);
    unpk2f(o2l, o2h, accP[4*d4+2]);
    unpk2f(o3l, o3h, accP[4*d4+3]);
    *reinterpret_cast<float4*>(op + 4*d4) = make_float4(
        (o0l+o0h)*inv, (o1l+o1h)*inv, (o2l+o2h)*inv, (o3l+o3h)*inv);
  }
}

// ---------------- last conv (60->12) fused with PixelShuffle(2) ------------
__global__ __launch_bounds__(256) void conv_out_kernel(
    const float* __restrict__ feat, const float* __restrict__ w,
    const float* __restrict__ b, float* __restrict__ out)
{
  int idx = blockIdx.x*256 + threadIdx.x;
  if (idx >= 2*3*256*256) return;
  int xq = idx & 255;
  int yq = (idx >> 8) & 255;
  int c  = (idx >> 16) % 3;
  int bq = idx / (3*65536);
  int co = c*4 + (yq & 1)*2 + (xq & 1);
  int hi = yq >> 1, wi = xq >> 1;
  float s = b[co];
  #pragma unroll
  for (int kh = 0; kh < 3; kh++){
    int hh = hi + kh - 1;
    if ((unsigned)hh > 127u) continue;
    #pragma unroll
    for (int kw = 0; kw < 3; kw++){
      int wwq = wi + kw - 1;
      if ((unsigned)wwq > 127u) continue;
      const float* fp = feat + (size_t)((bq*128 + hh)*128 + wwq)*60;
      const float* wp = w + ((size_t)co*60)*9 + kh*3 + kw;
      #pragma unroll
      for (int ci = 0; ci < 60; ci++)
        s = fmaf(fp[ci], wp[(size_t)ci*9], s);
    }
  }
  out[idx] = s;
}

// ---------------- launcher -------------------------------------------------
extern "C" void kernel_launch(void* const* d_in, const int* in_sizes, int n_in,
                              void* d_out, int out_size)
{
  const float* x      = (const float*)d_in[0];
  const float* conv_w = (const float*)d_in[1];
  const float* conv_b = (const float*)d_in[2];
  const float* ln1_g  = (const float*)d_in[3];
  const float* ln1_b  = (const float*)d_in[4];
  const float* qkv_w  = (const float*)d_in[5];
  const float* qkv_b  = (const float*)d_in[6];
  const float* proj_w = (const float*)d_in[7];
  const float* proj_b = (const float*)d_in[8];
  const float* ln2_g  = (const float*)d_in[9];
  const float* ln2_b  = (const float*)d_in[10];
  const float* fc1_w  = (const float*)d_in[11];
  const float* fc1_b  = (const float*)d_in[12];
  const float* fc2_w  = (const float*)d_in[13];
  const float* fc2_b  = (const float*)d_in[14];
  const float* last_w = (const float*)d_in[15];
  const float* last_b = (const float*)d_in[16];
  float* out = (float*)d_out;

  cudaFuncSetAttribute(fused_mlp_kernel,
                       cudaFuncAttributeMaxDynamicSharedMemorySize,
                       FMLP_SMEM_BYTES);

  float *feat, *qkvb, *attnb;
  cudaGetSymbolAddress((void**)&feat,  g_feat);
  cudaGetSymbolAddress((void**)&qkvb,  g_qkv);
  cudaGetSymbolAddress((void**)&attnb, g_attn);

  conv_in_kernel<<<(TOKENS*60 + 255)/256, 256>>>(x, conv_w, conv_b, feat);

  for (int l = 0; l < 36; l++){
    int i  = l % 6;
    int wi = i & 1;
    int wh = wi ? 8  : 32;
    int ww = wi ? 32 : 8;
    int shifted = (i % 4) >= 2;
    int sh = shifted ? (wi ? 4  : 16) : 0;
    int sw = shifted ? (wi ? 16 : 4 ) : 0;

    gemm_kernel<60,true,false><<<dim3(256,3), 480>>>(
        feat, qkv_w + (size_t)l*60*180, qkv_b + (size_t)l*180,
        ln1_g + (size_t)l*60, ln1_b + (size_t)l*60, qkvb, 180);

    if (shifted)
      attn_kernel<1><<<dim3(128,3), 256>>>(qkvb, attnb, wh, ww, sh, sw);
    else
      attn_kernel<0><<<dim3(128,3), 256>>>(qkvb, attnb, wh, ww, 0, 0);

    gemm_kernel<60,false,true><<<dim3(256,1), 480>>>(
        attnb, proj_w + (size_t)l*3600, proj_b + (size_t)l*60,
        nullptr, nullptr, feat, 60);

    fused_mlp_kernel<<<256, 480, FMLP_SMEM_BYTES>>>(
        feat, fc1_w + (size_t)l*7200, fc1_b + (size_t)l*120,
        fc2_w + (size_t)l*7200, fc2_b + (size_t)l*60,
        ln2_g + (size_t)l*60, ln2_b + (size_t)l*60);
  }

  conv_out_kernel<<<(2*3*256*256 + 255)/256, 256>>>(feat, last_w, last_b, out);
}

// round 9
// speedup vs baseline: 1.0228x; 1.0228x over previous
#include <cuda_runtime.h>
#include <cstdint>
#include <cstddef>

#define TOKENS (2*128*128)

// ---------------- scratch ---------------------------------------------------
__device__ float g_feat[TOKENS*60];
__device__ float g_qkv [TOKENS*180];
__device__ float g_attn[TOKENS*60];

// ---------------- FFMA-only exp / rcp ---------------------------------------
__device__ __forceinline__ float fexp(float x){
  x = fminf(fmaxf(x, -87.0f), 87.0f);
  float t  = x * 1.4426950408889634f;
  float kf = t + 12582912.0f;
  float i  = kf - 12582912.0f;
  float f  = t - i;
  float p  = 1.3333558e-3f;
  p = fmaf(p, f, 9.6181291e-3f);
  p = fmaf(p, f, 5.5504109e-2f);
  p = fmaf(p, f, 2.4022651e-1f);
  p = fmaf(p, f, 6.9314718e-1f);
  p = fmaf(p, f, 1.0f);
  int e = (int)i;
  return p * __int_as_float((e + 127) << 23);
}
__device__ __forceinline__ float frcp_nr(float y){
  float r = __int_as_float(0x7EF311C3u - __float_as_int(y));
  r = r * (2.0f - y * r);
  r = r * (2.0f - y * r);
  return r;
}

// ---------------- first conv ------------------------------------------------
__global__ __launch_bounds__(256) void conv_in_kernel(
    const float* __restrict__ x, const float* __restrict__ w,
    const float* __restrict__ b, float* __restrict__ feat)
{
  int idx = blockIdx.x*256 + threadIdx.x;
  if (idx >= TOKENS*60) return;
  int co = idx % 60;
  int t  = idx / 60;
  int wq = t & 127;
  int hq = (t >> 7) & 127;
  int bq = t >> 14;
  float s = b[co];
  #pragma unroll
  for (int kh = 0; kh < 3; kh++){
    int hh = hq + kh - 1;
    if ((unsigned)hh > 127u) continue;
    #pragma unroll
    for (int kw = 0; kw < 3; kw++){
      int wwq = wq + kw - 1;
      if ((unsigned)wwq > 127u) continue;
      const float* xp = x + (size_t)((bq*3)*128 + hh)*128 + wwq;
      #pragma unroll
      for (int ci = 0; ci < 3; ci++)
        s = fmaf(xp[(size_t)ci*128*128], w[((co*3+ci)*3+kh)*3+kw], s);
    }
  }
  feat[idx] = s;
}

// ---------------- persistent GEMM: K=60, 2 M-tiles/block ---------------------
// grid.x = 128; block handles tiles bx and bx+128 (128 rows each).
// W + LN params loaded once.  Tile-1 X prefetched into registers BEFORE
// tile-0's FMA loop (LDG latency hidden under compute).  Xs transposed
// [k][m] pad-132 => 16B-aligned LDS.128 a-loads in the hot loop.
template<bool DOLN, bool RESID>
__global__ __launch_bounds__(240, 2) void gemm_kernel(
    const float* __restrict__ X, const float* __restrict__ W,
    const float* __restrict__ bias,
    const float* __restrict__ lng, const float* __restrict__ lnb,
    float* __restrict__ Out, int Nfull)
{
  __shared__ float Xs[60][132];
  __shared__ float Ws[60][60];
  __shared__ float lg[60], lb[60];
  __shared__ float smu[128], srs[128];
  const int n0  = blockIdx.y * 60;
  const int tid = threadIdx.x;
  const int tx  = tid % 15;        // n group (4 cols)
  const int ty  = tid / 15;        // m group (8 rows)
  const int kk  = tid % 60;        // load lane: fixed k
  const int mb  = tid / 60;        // load lane: m base (0..3)

  // W tile + LN params: once per block
  #pragma unroll
  for (int idx = tid; idx < 3600; idx += 240){
    int k = idx / 60, n = idx - k*60;
    Ws[k][n] = W[(size_t)k*Nfull + n0 + n];
  }
  if (DOLN && tid < 60){ lg[tid] = lng[tid]; lb[tid] = lnb[tid]; }

  // prefetch tile 0
  float xreg[32];
  {
    const int m0 = blockIdx.x * 128;
    #pragma unroll
    for (int i = 0; i < 32; i++)
      xreg[i] = X[(size_t)(m0 + mb + i*4)*60 + kk];
  }

  #pragma unroll
  for (int t = 0; t < 2; t++){
    const int m0 = (blockIdx.x + t*128) * 128;

    // stage regs -> smem (transposed)
    #pragma unroll
    for (int i = 0; i < 32; i++)
      Xs[kk][mb + i*4] = xreg[i];
    __syncthreads();

    // prefetch tile 1 while tile 0 computes
    if (t == 0){
      const int m1 = (blockIdx.x + 128) * 128;
      #pragma unroll
      for (int i = 0; i < 32; i++)
        xreg[i] = X[(size_t)(m1 + mb + i*4)*60 + kk];
    }

    if (DOLN){
      if (tid < 128){
        float mu = 0.f;
        #pragma unroll
        for (int c = 0; c < 60; c++) mu += Xs[c][tid];
        mu *= (1.0f/60.0f);
        float var = 0.f;
        #pragma unroll
        for (int c = 0; c < 60; c++){ float d = Xs[c][tid]-mu; var = fmaf(d,d,var); }
        smu[tid] = mu;
        srs[tid] = rsqrtf(var*(1.0f/60.0f) + 1e-5f);
      }
      __syncthreads();
      // normalize distributed over all 240 threads
      for (int idx = tid; idx < 60*128; idx += 240){
        int c = idx >> 7, m = idx & 127;
        Xs[c][m] = (Xs[c][m]-smu[m])*srs[m]*lg[c] + lb[c];
      }
      __syncthreads();
    }

    float acc[8][4];
    #pragma unroll
    for (int i = 0; i < 8; i++)
      #pragma unroll
      for (int j = 0; j < 4; j++) acc[i][j] = 0.f;

    #pragma unroll 12
    for (int k = 0; k < 60; k++){
      float4 b4 = *reinterpret_cast<const float4*>(&Ws[k][tx*4]);
      float a[8];
      #pragma unroll
      for (int i = 0; i < 8; i++) a[i] = Xs[k][ty*8+i];
      #pragma unroll
      for (int i = 0; i < 8; i++){
        acc[i][0] = fmaf(a[i], b4.x, acc[i][0]);
        acc[i][1] = fmaf(a[i], b4.y, acc[i][1]);
        acc[i][2] = fmaf(a[i], b4.z, acc[i][2]);
        acc[i][3] = fmaf(a[i], b4.w, acc[i][3]);
      }
    }

    float4 bb = *reinterpret_cast<const float4*>(&bias[n0 + tx*4]);
    #pragma unroll
    for (int i = 0; i < 8; i++){
      size_t o = (size_t)(m0 + ty*8 + i) * Nfull + n0 + tx*4;
      float v0 = acc[i][0] + bb.x;
      float v1 = acc[i][1] + bb.y;
      float v2 = acc[i][2] + bb.z;
      float v3 = acc[i][3] + bb.w;
      if (RESID){
        float4 old = *reinterpret_cast<const float4*>(&Out[o]);
        v0 += old.x; v1 += old.y; v2 += old.z; v3 += old.w;
      }
      *reinterpret_cast<float4*>(&Out[o]) = make_float4(v0, v1, v2, v3);
    }
    if (t == 0) __syncthreads();   // all reads of Xs done before overwrite
  }
}

// ---------------- fused MLP (round-6 version, scalar FFMA) ------------------
#define FMLP_SMEM_BYTES (22680*4)
__global__ __launch_bounds__(240, 2) void fused_mlp_kernel(
    float* __restrict__ feat,
    const float* __restrict__ W1, const float* __restrict__ b1,
    const float* __restrict__ W2, const float* __restrict__ b2,
    const float* __restrict__ lng, const float* __restrict__ lnb)
{
  extern __shared__ float pool[];
  float* Xs  = pool;           // [60][129]
  float* Ws1 = pool + 7740;    // [60][120]
  float* hs  = pool;           // [120][129] (union after stage A)
  float* Ws2 = pool + 15480;   // [120][60]
  __shared__ float lg[60], lb[60];

  const int m0  = blockIdx.x * 128;
  const int tid = threadIdx.x;
  const int tx  = tid % 15;
  const int ty  = tid / 15;

  if (tid < 60){ lg[tid] = lng[tid]; lb[tid] = lnb[tid]; }

  #pragma unroll
  for (int idx = tid; idx < 128*60; idx += 240){
    int m = idx / 60, k = idx - m*60;
    Xs[k*129 + m] = feat[(size_t)(m0+m)*60 + k];
  }
  #pragma unroll
  for (int idx = tid; idx < 60*120; idx += 240) Ws1[idx] = W1[idx];
  #pragma unroll
  for (int idx = tid; idx < 120*60; idx += 240) Ws2[idx] = W2[idx];
  __syncthreads();

  if (tid < 128){
    float mu = 0.f;
    #pragma unroll
    for (int c = 0; c < 60; c++) mu += Xs[c*129 + tid];
    mu *= (1.0f/60.0f);
    float var = 0.f;
    #pragma unroll
    for (int c = 0; c < 60; c++){ float d = Xs[c*129 + tid]-mu; var = fmaf(d,d,var); }
    float rs = rsqrtf(var*(1.0f/60.0f) + 1e-5f);
    #pragma unroll
    for (int c = 0; c < 60; c++)
      Xs[c*129 + tid] = (Xs[c*129 + tid]-mu)*rs*lg[c] + lb[c];
  }
  __syncthreads();

  float acc[8][8];
  #pragma unroll
  for (int i = 0; i < 8; i++)
    #pragma unroll
    for (int j = 0; j < 8; j++) acc[i][j] = 0.f;

  #pragma unroll 4
  for (int k = 0; k < 60; k++){
    float4 bA = *reinterpret_cast<const float4*>(&Ws1[k*120 + tx*8]);
    float4 bB = *reinterpret_cast<const float4*>(&Ws1[k*120 + tx*8 + 4]);
    float a[8];
    #pragma unroll
    for (int i = 0; i < 8; i++) a[i] = Xs[k*129 + ty*8 + i];
    #pragma unroll
    for (int i = 0; i < 8; i++){
      acc[i][0] = fmaf(a[i], bA.x, acc[i][0]);
      acc[i][1] = fmaf(a[i], bA.y, acc[i][1]);
      acc[i][2] = fmaf(a[i], bA.z, acc[i][2]);
      acc[i][3] = fmaf(a[i], bA.w, acc[i][3]);
      acc[i][4] = fmaf(a[i], bB.x, acc[i][4]);
      acc[i][5] = fmaf(a[i], bB.y, acc[i][5]);
      acc[i][6] = fmaf(a[i], bB.z, acc[i][6]);
      acc[i][7] = fmaf(a[i], bB.w, acc[i][7]);
    }
  }

  float4 b1a = *reinterpret_cast<const float4*>(&b1[tx*8]);
  float4 b1b = *reinterpret_cast<const float4*>(&b1[tx*8 + 4]);
  float bb1[8] = {b1a.x,b1a.y,b1a.z,b1a.w,b1b.x,b1b.y,b1b.z,b1b.w};
  #pragma unroll
  for (int i = 0; i < 8; i++)
    #pragma unroll
    for (int j = 0; j < 8; j++){
      float v = acc[i][j] + bb1[j];
      acc[i][j] = v * frcp_nr(1.0f + fexp(-v));
    }

  __syncthreads();

  #pragma unroll
  for (int j = 0; j < 8; j++)
    #pragma unroll
    for (int i = 0; i < 8; i++)
      hs[(tx*8 + j)*129 + ty*8 + i] = acc[i][j];
  __syncthreads();

  float acc2[8][4];
  #pragma unroll
  for (int i = 0; i < 8; i++)
    #pragma unroll
    for (int j = 0; j < 4; j++) acc2[i][j] = 0.f;

  #pragma unroll 6
  for (int k = 0; k < 120; k++){
    float4 b4 = *reinterpret_cast<const float4*>(&Ws2[k*60 + tx*4]);
    float a[8];
    #pragma unroll
    for (int i = 0; i < 8; i++) a[i] = hs[k*129 + ty*8 + i];
    #pragma unroll
    for (int i = 0; i < 8; i++){
      acc2[i][0] = fmaf(a[i], b4.x, acc2[i][0]);
      acc2[i][1] = fmaf(a[i], b4.y, acc2[i][1]);
      acc2[i][2] = fmaf(a[i], b4.z, acc2[i][2]);
      acc2[i][3] = fmaf(a[i], b4.w, acc2[i][3]);
    }
  }

  float4 bb2 = *reinterpret_cast<const float4*>(&b2[tx*4]);
  #pragma unroll
  for (int i = 0; i < 8; i++){
    size_t o = (size_t)(m0 + ty*8 + i) * 60 + tx*4;
    float4 old = *reinterpret_cast<const float4*>(&feat[o]);
    *reinterpret_cast<float4*>(&feat[o]) = make_float4(
        old.x + acc2[i][0] + bb2.x, old.y + acc2[i][1] + bb2.y,
        old.z + acc2[i][2] + bb2.z, old.w + acc2[i][3] + bb2.w);
  }
}

// ---------------- windowed attention (round-6 version) ----------------------
__global__ __launch_bounds__(256) void attn_kernel(
    const float* __restrict__ qkv, float* __restrict__ out,
    int wh, int ww, int sh, int sw, int masked)
{
  __shared__ float4 ks4[256][5];
  __shared__ float4 vs4[256][5];
  __shared__ int    rid[256];
  const int win  = blockIdx.x;
  const int head = blockIdx.y;
  const int nWc = 128 / ww;
  const int nHc = 128 / wh;
  const int b   = win / (nHc*nWc);
  const int rem = win % (nHc*nWc);
  const int ih  = rem / nWc, iw = rem % nWc;
  const int n   = threadIdx.x;
  const int r   = n / ww, col = n % ww;
  const int h   = ih*wh + r, w = iw*ww + col;
  const int gh  = (h + sh) & 127, gw = (w + sw) & 127;
  const int gidx = (b*128 + gh)*128 + gw;
  const float4* bp4 = reinterpret_cast<const float4*>(qkv + (size_t)gidx*180 + head*20);

  const float scale = 0.223606797749979f;
  float4 q4[5];
  #pragma unroll
  for (int d = 0; d < 5; d++){
    float4 qv = bp4[d];
    qv.x *= scale; qv.y *= scale; qv.z *= scale; qv.w *= scale;
    q4[d]     = qv;
    ks4[n][d] = bp4[15+d];
    vs4[n][d] = bp4[30+d];
  }
  int rh = (h < 128-wh) ? 0 : ((h < 128-sh) ? 1 : 2);
  int rw = (w < 128-ww) ? 0 : ((w < 128-sw) ? 1 : 2);
  rid[n] = rh*3 + rw;
  __syncthreads();

  const int myrid = rid[n];
  float m = -3.0e38f, l = 0.f;
  float4 a4[5];
  #pragma unroll
  for (int d = 0; d < 5; d++) a4[d] = make_float4(0.f,0.f,0.f,0.f);

  for (int j = 0; j < 256; j++){
    float s = 0.f;
    #pragma unroll
    for (int d = 0; d < 5; d++){
      float4 kk = ks4[j][d];
      s = fmaf(q4[d].x, kk.x, s);
      s = fmaf(q4[d].y, kk.y, s);
      s = fmaf(q4[d].z, kk.z, s);
      s = fmaf(q4[d].w, kk.w, s);
    }
    if (masked && rid[j] != myrid) s -= 100.0f;
    float m2 = fmaxf(m, s);
    if (m2 > m){
      float alpha = fexp(m - m2);
      l *= alpha;
      #pragma unroll
      for (int d = 0; d < 5; d++){
        a4[d].x *= alpha; a4[d].y *= alpha; a4[d].z *= alpha; a4[d].w *= alpha;
      }
      m = m2;
    }
    float p = fexp(s - m);
    l += p;
    #pragma unroll
    for (int d = 0; d < 5; d++){
      float4 vv = vs4[j][d];
      a4[d].x = fmaf(p, vv.x, a4[d].x);
      a4[d].y = fmaf(p, vv.y, a4[d].y);
      a4[d].z = fmaf(p, vv.z, a4[d].z);
      a4[d].w = fmaf(p, vv.w, a4[d].w);
    }
  }
  float inv = 1.0f / l;
  float4* op4 = reinterpret_cast<float4*>(out + (size_t)gidx*60 + head*20);
  #pragma unroll
  for (int d = 0; d < 5; d++){
    float4 v = a4[d];
    v.x *= inv; v.y *= inv; v.z *= inv; v.w *= inv;
    op4[d] = v;
  }
}

// ---------------- last conv (60->12) fused with PixelShuffle(2) ------------
__global__ __launch_bounds__(256) void conv_out_kernel(
    const float* __restrict__ feat, const float* __restrict__ w,
    const float* __restrict__ b, float* __restrict__ out)
{
  int idx = blockIdx.x*256 + threadIdx.x;
  if (idx >= 2*3*256*256) return;
  int xq = idx & 255;
  int yq = (idx >> 8) & 255;
  int c  = (idx >> 16) % 3;
  int bq = idx / (3*65536);
  int co = c*4 + (yq & 1)*2 + (xq & 1);
  int hi = yq >> 1, wi = xq >> 1;
  float s = b[co];
  #pragma unroll
  for (int kh = 0; kh < 3; kh++){
    int hh = hi + kh - 1;
    if ((unsigned)hh > 127u) continue;
    #pragma unroll
    for (int kw = 0; kw < 3; kw++){
      int wwq = wi + kw - 1;
      if ((unsigned)wwq > 127u) continue;
      const float* fp = feat + (size_t)((bq*128 + hh)*128 + wwq)*60;
      const float* wp = w + ((size_t)co*60)*9 + kh*3 + kw;
      #pragma unroll
      for (int ci = 0; ci < 60; ci++)
        s = fmaf(fp[ci], wp[(size_t)ci*9], s);
    }
  }
  out[idx] = s;
}

// ---------------- launcher -------------------------------------------------
extern "C" void kernel_launch(void* const* d_in, const int* in_sizes, int n_in,
                              void* d_out, int out_size)
{
  const float* x      = (const float*)d_in[0];
  const float* conv_w = (const float*)d_in[1];
  const float* conv_b = (const float*)d_in[2];
  const float* ln1_g  = (const float*)d_in[3];
  const float* ln1_b  = (const float*)d_in[4];
  const float* qkv_w  = (const float*)d_in[5];
  const float* qkv_b  = (const float*)d_in[6];
  const float* proj_w = (const float*)d_in[7];
  const float* proj_b = (const float*)d_in[8];
  const float* ln2_g  = (const float*)d_in[9];
  const float* ln2_b  = (const float*)d_in[10];
  const float* fc1_w  = (const float*)d_in[11];
  const float* fc1_b  = (const float*)d_in[12];
  const float* fc2_w  = (const float*)d_in[13];
  const float* fc2_b  = (const float*)d_in[14];
  const float* last_w = (const float*)d_in[15];
  const float* last_b = (const float*)d_in[16];
  float* out = (float*)d_out;

  cudaFuncSetAttribute(fused_mlp_kernel,
                       cudaFuncAttributeMaxDynamicSharedMemorySize,
                       FMLP_SMEM_BYTES);

  float *feat, *qkvb, *attnb;
  cudaGetSymbolAddress((void**)&feat,  g_feat);
  cudaGetSymbolAddress((void**)&qkvb,  g_qkv);
  cudaGetSymbolAddress((void**)&attnb, g_attn);

  conv_in_kernel<<<(TOKENS*60 + 255)/256, 256>>>(x, conv_w, conv_b, feat);

  for (int l = 0; l < 36; l++){
    int i  = l % 6;
    int wi = i & 1;
    int wh = wi ? 8  : 32;
    int ww = wi ? 32 : 8;
    int shifted = (i % 4) >= 2;
    int sh = shifted ? (wi ? 4  : 16) : 0;
    int sw = shifted ? (wi ? 16 : 4 ) : 0;

    // LN1 + QKV (persistent, 2 tiles/block)
    gemm_kernel<true,false><<<dim3(128,3), 240>>>(
        feat, qkv_w + (size_t)l*60*180, qkv_b + (size_t)l*180,
        ln1_g + (size_t)l*60, ln1_b + (size_t)l*60, qkvb, 180);

    attn_kernel<<<dim3(128,3), 256>>>(qkvb, attnb, wh, ww, sh, sw, shifted);

    // proj + residual (persistent, 2 tiles/block)
    gemm_kernel<false,true><<<dim3(128,1), 240>>>(
        attnb, proj_w + (size_t)l*3600, proj_b + (size_t)l*60,
        nullptr, nullptr, feat, 60);

    fused_mlp_kernel<<<256, 240, FMLP_SMEM_BYTES>>>(
        feat, fc1_w + (size_t)l*7200, fc1_b + (size_t)l*120,
        fc2_w + (size_t)l*7200, fc2_b + (size_t)l*60,
        ln2_g + (size_t)l*60, ln2_b + (size_t)l*60);
  }

  conv_out_kernel<<<(2*3*256*256 + 255)/256, 256>>>(feat, last_w, last_b, out);
}

// round 17
// speedup vs baseline: 1.5782x; 1.5430x over previous
#include <cuda_runtime.h>
#include <cstdint>
#include <cstddef>

#define TOKENS (2*128*128)

// ---------------- scratch ---------------------------------------------------
__device__ float g_feat[TOKENS*60];
__device__ float g_qkv [TOKENS*180];
__device__ float g_attn[TOKENS*60];

// ---------------- FFMA-only exp / rcp ---------------------------------------
__device__ __forceinline__ float fexp(float x){
  x = fminf(fmaxf(x, -87.0f), 87.0f);
  float t  = x * 1.4426950408889634f;
  float kf = t + 12582912.0f;
  float i  = kf - 12582912.0f;
  float f  = t - i;
  float p  = 1.3333558e-3f;
  p = fmaf(p, f, 9.6181291e-3f);
  p = fmaf(p, f, 5.5504109e-2f);
  p = fmaf(p, f, 2.4022651e-1f);
  p = fmaf(p, f, 6.9314718e-1f);
  p = fmaf(p, f, 1.0f);
  int e = (int)i;
  return p * __int_as_float((e + 127) << 23);
}
__device__ __forceinline__ float frcp_nr(float y){
  float r = __int_as_float(0x7EF311C3u - __float_as_int(y));
  r = r * (2.0f - y * r);
  r = r * (2.0f - y * r);
  return r;
}

// 2^t via magic-round splice; valid for t in ~(-120, 120), no clamp needed.
__device__ __forceinline__ float exp2m(float t){
  float kf = t + 12582912.0f;
  float fi = kf - 12582912.0f;
  float f  = t - fi;
  float p  = 1.3333558e-3f;
  p = fmaf(p, f, 9.6181291e-3f);
  p = fmaf(p, f, 5.5504109e-2f);
  p = fmaf(p, f, 2.4022651e-1f);
  p = fmaf(p, f, 6.9314718e-1f);
  p = fmaf(p, f, 1.0f);
  int ib = __float_as_int(kf) << 23;   // == i << 23 (low 9 bits of magic are 0)
  return __int_as_float(__float_as_int(p) + ib);
}

__device__ __forceinline__ unsigned cvt_tf32(float x){
  unsigned u; asm("cvt.rna.tf32.f32 %0, %1;" : "=r"(u) : "f"(x)); return u;
}

__device__ __forceinline__ void mma_tf32(float* c, const unsigned* a,
                                         unsigned b0, unsigned b1){
  asm volatile(
    "mma.sync.aligned.m16n8k8.row.col.f32.tf32.tf32.f32 "
    "{%0,%1,%2,%3}, {%4,%5,%6,%7}, {%8,%9}, {%0,%1,%2,%3};"
    : "+f"(c[0]), "+f"(c[1]), "+f"(c[2]), "+f"(c[3])
    : "r"(a[0]), "r"(a[1]), "r"(a[2]), "r"(a[3]), "r"(b0), "r"(b1));
}

// ---------------- first conv ------------------------------------------------
__global__ __launch_bounds__(256) void conv_in_kernel(
    const float* __restrict__ x, const float* __restrict__ w,
    const float* __restrict__ b, float* __restrict__ feat)
{
  int idx = blockIdx.x*256 + threadIdx.x;
  if (idx >= TOKENS*60) return;
  int co = idx % 60;
  int t  = idx / 60;
  int wq = t & 127;
  int hq = (t >> 7) & 127;
  int bq = t >> 14;
  float s = b[co];
  #pragma unroll
  for (int kh = 0; kh < 3; kh++){
    int hh = hq + kh - 1;
    if ((unsigned)hh > 127u) continue;
    #pragma unroll
    for (int kw = 0; kw < 3; kw++){
      int wwq = wq + kw - 1;
      if ((unsigned)wwq > 127u) continue;
      const float* xp = x + (size_t)((bq*3)*128 + hh)*128 + wwq;
      #pragma unroll
      for (int ci = 0; ci < 3; ci++)
        s = fmaf(xp[(size_t)ci*128*128], w[((co*3+ci)*3+kh)*3+kw], s);
    }
  }
  feat[idx] = s;
}

// ---------------- GEMM (round-6 exact: 128Mx60N, 240 thr, 8x4 tile) --------
template<int K, bool DOLN, bool RESID>
__global__ __launch_bounds__(240) void gemm_kernel(
    const float* __restrict__ X, const float* __restrict__ W,
    const float* __restrict__ bias,
    const float* __restrict__ lng, const float* __restrict__ lnb,
    float* __restrict__ Out, int Nfull)
{
  static_assert(!(DOLN && K != 60), "LN fusion only for K=60");
  __shared__ float Xs[60][129];
  __shared__ float Ws[60][60];
  __shared__ float lg[60], lb[60];
  const int m0  = blockIdx.x * 128;
  const int n0  = blockIdx.y * 60;
  const int tid = threadIdx.x;
  const int tx  = tid % 15;
  const int ty  = tid / 15;

  if (DOLN && tid < 60){ lg[tid] = lng[tid]; lb[tid] = lnb[tid]; }

  float acc[8][4];
  #pragma unroll
  for (int i = 0; i < 8; i++)
    #pragma unroll
    for (int j = 0; j < 4; j++) acc[i][j] = 0.f;

  for (int k0 = 0; k0 < K; k0 += 60){
    #pragma unroll
    for (int idx = tid; idx < 128*60; idx += 240){
      int m = idx / 60, k = idx - m*60;
      Xs[k][m] = X[(size_t)(m0+m)*K + k0 + k];
    }
    #pragma unroll
    for (int idx = tid; idx < 60*60; idx += 240){
      int k = idx / 60, n = idx - k*60;
      Ws[k][n] = W[(size_t)(k0+k)*Nfull + n0 + n];
    }
    __syncthreads();
    if (DOLN){
      if (tid < 128){
        float mu = 0.f;
        #pragma unroll
        for (int c = 0; c < 60; c++) mu += Xs[c][tid];
        mu *= (1.0f/60.0f);
        float var = 0.f;
        #pragma unroll
        for (int c = 0; c < 60; c++){ float d = Xs[c][tid]-mu; var = fmaf(d,d,var); }
        float rs = rsqrtf(var*(1.0f/60.0f) + 1e-5f);
        #pragma unroll
        for (int c = 0; c < 60; c++)
          Xs[c][tid] = (Xs[c][tid]-mu)*rs*lg[c] + lb[c];
      }
      __syncthreads();
    }
    #pragma unroll 12
    for (int k = 0; k < 60; k++){
      float4 b4 = *reinterpret_cast<const float4*>(&Ws[k][tx*4]);
      float a[8];
      #pragma unroll
      for (int i = 0; i < 8; i++) a[i] = Xs[k][ty*8+i];
      #pragma unroll
      for (int i = 0; i < 8; i++){
        acc[i][0] = fmaf(a[i], b4.x, acc[i][0]);
        acc[i][1] = fmaf(a[i], b4.y, acc[i][1]);
        acc[i][2] = fmaf(a[i], b4.z, acc[i][2]);
        acc[i][3] = fmaf(a[i], b4.w, acc[i][3]);
      }
    }
    __syncthreads();
  }

  float4 bb = *reinterpret_cast<const float4*>(&bias[n0 + tx*4]);
  #pragma unroll
  for (int i = 0; i < 8; i++){
    size_t o = (size_t)(m0 + ty*8 + i) * Nfull + n0 + tx*4;
    float v0 = acc[i][0] + bb.x;
    float v1 = acc[i][1] + bb.y;
    float v2 = acc[i][2] + bb.z;
    float v3 = acc[i][3] + bb.w;
    if (RESID){
      float4 old = *reinterpret_cast<const float4*>(&Out[o]);
      v0 += old.x; v1 += old.y; v2 += old.z; v3 += old.w;
    }
    *reinterpret_cast<float4*>(&Out[o]) = make_float4(v0, v1, v2, v3);
  }
}

// ---------------- fused MLP (round-6 exact) ---------------------------------
#define FMLP_SMEM_BYTES (22680*4)
__global__ __launch_bounds__(240, 2) void fused_mlp_kernel(
    float* __restrict__ feat,
    const float* __restrict__ W1, const float* __restrict__ b1,
    const float* __restrict__ W2, const float* __restrict__ b2,
    const float* __restrict__ lng, const float* __restrict__ lnb)
{
  extern __shared__ float pool[];
  float* Xs  = pool;
  float* Ws1 = pool + 7740;
  float* hs  = pool;
  float* Ws2 = pool + 15480;
  __shared__ float lg[60], lb[60];

  const int m0  = blockIdx.x * 128;
  const int tid = threadIdx.x;
  const int tx  = tid % 15;
  const int ty  = tid / 15;

  if (tid < 60){ lg[tid] = lng[tid]; lb[tid] = lnb[tid]; }

  #pragma unroll
  for (int idx = tid; idx < 128*60; idx += 240){
    int m = idx / 60, k = idx - m*60;
    Xs[k*129 + m] = feat[(size_t)(m0+m)*60 + k];
  }
  #pragma unroll
  for (int idx = tid; idx < 60*120; idx += 240) Ws1[idx] = W1[idx];
  #pragma unroll
  for (int idx = tid; idx < 120*60; idx += 240) Ws2[idx] = W2[idx];
  __syncthreads();

  if (tid < 128){
    float mu = 0.f;
    #pragma unroll
    for (int c = 0; c < 60; c++) mu += Xs[c*129 + tid];
    mu *= (1.0f/60.0f);
    float var = 0.f;
    #pragma unroll
    for (int c = 0; c < 60; c++){ float d = Xs[c*129 + tid]-mu; var = fmaf(d,d,var); }
    float rs = rsqrtf(var*(1.0f/60.0f) + 1e-5f);
    #pragma unroll
    for (int c = 0; c < 60; c++)
      Xs[c*129 + tid] = (Xs[c*129 + tid]-mu)*rs*lg[c] + lb[c];
  }
  __syncthreads();

  float acc[8][8];
  #pragma unroll
  for (int i = 0; i < 8; i++)
    #pragma unroll
    for (int j = 0; j < 8; j++) acc[i][j] = 0.f;

  #pragma unroll 4
  for (int k = 0; k < 60; k++){
    float4 bA = *reinterpret_cast<const float4*>(&Ws1[k*120 + tx*8]);
    float4 bB = *reinterpret_cast<const float4*>(&Ws1[k*120 + tx*8 + 4]);
    float a[8];
    #pragma unroll
    for (int i = 0; i < 8; i++) a[i] = Xs[k*129 + ty*8 + i];
    #pragma unroll
    for (int i = 0; i < 8; i++){
      acc[i][0] = fmaf(a[i], bA.x, acc[i][0]);
      acc[i][1] = fmaf(a[i], bA.y, acc[i][1]);
      acc[i][2] = fmaf(a[i], bA.z, acc[i][2]);
      acc[i][3] = fmaf(a[i], bA.w, acc[i][3]);
      acc[i][4] = fmaf(a[i], bB.x, acc[i][4]);
      acc[i][5] = fmaf(a[i], bB.y, acc[i][5]);
      acc[i][6] = fmaf(a[i], bB.z, acc[i][6]);
      acc[i][7] = fmaf(a[i], bB.w, acc[i][7]);
    }
  }

  float4 b1a = *reinterpret_cast<const float4*>(&b1[tx*8]);
  float4 b1b = *reinterpret_cast<const float4*>(&b1[tx*8 + 4]);
  float bb1[8] = {b1a.x,b1a.y,b1a.z,b1a.w,b1b.x,b1b.y,b1b.z,b1b.w};
  #pragma unroll
  for (int i = 0; i < 8; i++)
    #pragma unroll
    for (int j = 0; j < 8; j++){
      float v = acc[i][j] + bb1[j];
      acc[i][j] = v * frcp_nr(1.0f + fexp(-v));
    }

  __syncthreads();

  #pragma unroll
  for (int j = 0; j < 8; j++)
    #pragma unroll
    for (int i = 0; i < 8; i++)
      hs[(tx*8 + j)*129 + ty*8 + i] = acc[i][j];
  __syncthreads();

  float acc2[8][4];
  #pragma unroll
  for (int i = 0; i < 8; i++)
    #pragma unroll
    for (int j = 0; j < 4; j++) acc2[i][j] = 0.f;

  #pragma unroll 6
  for (int k = 0; k < 120; k++){
    float4 b4 = *reinterpret_cast<const float4*>(&Ws2[k*60 + tx*4]);
    float a[8];
    #pragma unroll
    for (int i = 0; i < 8; i++) a[i] = hs[k*129 + ty*8 + i];
    #pragma unroll
    for (int i = 0; i < 8; i++){
      acc2[i][0] = fmaf(a[i], b4.x, acc2[i][0]);
      acc2[i][1] = fmaf(a[i], b4.y, acc2[i][1]);
      acc2[i][2] = fmaf(a[i], b4.z, acc2[i][2]);
      acc2[i][3] = fmaf(a[i], b4.w, acc2[i][3]);
    }
  }

  float4 bb2 = *reinterpret_cast<const float4*>(&b2[tx*4]);
  #pragma unroll
  for (int i = 0; i < 8; i++){
    size_t o = (size_t)(m0 + ty*8 + i) * 60 + tx*4;
    float4 old = *reinterpret_cast<const float4*>(&feat[o]);
    *reinterpret_cast<float4*>(&feat[o]) = make_float4(
        old.x + acc2[i][0] + bb2.x, old.y + acc2[i][1] + bb2.y,
        old.z + acc2[i][2] + bb2.z, old.w + acc2[i][3] + bb2.w);
  }
}

// ---------------- tf32 MMA windowed attention --------------------------------
// Block = (window, head), 8 warps; warp owns 32 Q rows.  K dim 20 padded->24.
// S = Q@K^T (24 MMAs per 32-key j-block), mask+exp2 in C-frags, P C->A via
// intra-quad shuffles (no smem, no barriers), O += P@[V|1] (denominator from
// the ones column).  Softmax without max-subtraction (scores bounded; masked
// entries get -80 in log2 domain -> 2^-80 ~ 0).
#define ATTN_SMEM_BYTES (19136*4)

template<int MASKED>
__global__ __launch_bounds__(256) void attn_kernel(
    const float* __restrict__ qkv, float* __restrict__ out,
    int wh, int ww, int sh, int sw)
{
  extern __shared__ float apool[];
  float* Qs  = apool;            // [256][25]  (tf32 bits, pre-scaled)
  float* Vs  = apool + 6400;     // [256][25]  col20 = 1.0 (denominator)
  float* KsT = apool + 12800;    // [24][264]  transposed K
  __shared__ int rid[256];
  __shared__ int gidxs[256];

  const int win  = blockIdx.x;
  const int head = blockIdx.y;
  const int nWc = 128 / ww;
  const int nHc = 128 / wh;
  const int b   = win / (nHc*nWc);
  const int rem = win % (nHc*nWc);
  const int ih  = rem / nWc, iw = rem % nWc;
  const int n   = threadIdx.x;
  const int lane = n & 31;
  const int warp = n >> 5;

  // ---- stage Q,K,V (one token per thread) ----
  {
    const int r = n / ww, col = n % ww;
    const int h = ih*wh + r, w = iw*ww + col;
    const int gh = (h + sh) & 127, gw = (w + sw) & 127;
    const int gidx = (b*128 + gh)*128 + gw;
    gidxs[n] = gidx;
    int rh = (h < 128-wh) ? 0 : ((h < 128-sh) ? 1 : 2);
    int rw = (w < 128-ww) ? 0 : ((w < 128-sw) ? 1 : 2);
    rid[n] = rh*3 + rw;

    const float4* bp4 = reinterpret_cast<const float4*>(qkv + (size_t)gidx*180 + head*20);
    const float qsc = 0.223606797749979f * 1.4426950408889634f;  // hd^-0.5 * log2e
    #pragma unroll
    for (int d4 = 0; d4 < 5; d4++){
      float4 qv = bp4[d4];
      float4 kv = bp4[15+d4];
      float4 vv = bp4[30+d4];
      Qs[n*25 + 4*d4+0] = __uint_as_float(cvt_tf32(qv.x*qsc));
      Qs[n*25 + 4*d4+1] = __uint_as_float(cvt_tf32(qv.y*qsc));
      Qs[n*25 + 4*d4+2] = __uint_as_float(cvt_tf32(qv.z*qsc));
      Qs[n*25 + 4*d4+3] = __uint_as_float(cvt_tf32(qv.w*qsc));
      KsT[(4*d4+0)*264 + n] = __uint_as_float(cvt_tf32(kv.x));
      KsT[(4*d4+1)*264 + n] = __uint_as_float(cvt_tf32(kv.y));
      KsT[(4*d4+2)*264 + n] = __uint_as_float(cvt_tf32(kv.z));
      KsT[(4*d4+3)*264 + n] = __uint_as_float(cvt_tf32(kv.w));
      Vs[n*25 + 4*d4+0] = __uint_as_float(cvt_tf32(vv.x));
      Vs[n*25 + 4*d4+1] = __uint_as_float(cvt_tf32(vv.y));
      Vs[n*25 + 4*d4+2] = __uint_as_float(cvt_tf32(vv.z));
      Vs[n*25 + 4*d4+3] = __uint_as_float(cvt_tf32(vv.w));
    }
    #pragma unroll
    for (int d = 20; d < 24; d++){
      Qs[n*25 + d]   = 0.f;
      KsT[d*264 + n] = 0.f;
    }
    Vs[n*25 + 20] = 1.0f;            // ones column -> rowsum
    Vs[n*25 + 21] = 0.f; Vs[n*25 + 22] = 0.f; Vs[n*25 + 23] = 0.f;
  }
  __syncthreads();

  const int m0w = warp * 32;
  const int lq  = lane & 3;          // threadID in quad
  const int lr  = lane >> 2;         // row in group

  int rq[2][2];
  if (MASKED){
    #pragma unroll
    for (int mt = 0; mt < 2; mt++){
      rq[mt][0] = rid[m0w + mt*16 + lr];
      rq[mt][1] = rid[m0w + mt*16 + lr + 8];
    }
  }

  float oc[2][3][4];
  #pragma unroll
  for (int mt = 0; mt < 2; mt++)
    #pragma unroll
    for (int nt = 0; nt < 3; nt++)
      #pragma unroll
      for (int i = 0; i < 4; i++) oc[mt][nt][i] = 0.f;

  const int src1 = (lane & 28) | (lq >> 1);
  const int src2 = src1 | 2;
  const bool oddc = lq & 1;

  for (int jb = 0; jb < 8; jb++){
    const int kb = jb * 32;

    // ---- S = Q @ K^T ----
    float sc[2][4][4];
    #pragma unroll
    for (int mt = 0; mt < 2; mt++)
      #pragma unroll
      for (int nt = 0; nt < 4; nt++)
        #pragma unroll
        for (int i = 0; i < 4; i++) sc[mt][nt][i] = 0.f;

    #pragma unroll
    for (int kt = 0; kt < 3; kt++){
      unsigned a[2][4];
      #pragma unroll
      for (int mt = 0; mt < 2; mt++){
        int rowb = (m0w + mt*16 + lr) * 25 + kt*8 + lq;
        a[mt][0] = __float_as_uint(Qs[rowb]);
        a[mt][1] = __float_as_uint(Qs[rowb + 8*25]);
        a[mt][2] = __float_as_uint(Qs[rowb + 4]);
        a[mt][3] = __float_as_uint(Qs[rowb + 8*25 + 4]);
      }
      #pragma unroll
      for (int nt = 0; nt < 4; nt++){
        int cb = kb + nt*8 + lr;
        unsigned b0 = __float_as_uint(KsT[(kt*8 + lq)*264 + cb]);
        unsigned b1 = __float_as_uint(KsT[(kt*8 + lq + 4)*264 + cb]);
        mma_tf32(sc[0][nt], a[0], b0, b1);
        mma_tf32(sc[1][nt], a[1], b0, b1);
      }
    }

    // ---- mask + exp2 ----
    #pragma unroll
    for (int nt = 0; nt < 4; nt++){
      int ck0 = 0, ck1 = 0;
      if (MASKED){
        ck0 = rid[kb + nt*8 + 2*lq];
        ck1 = rid[kb + nt*8 + 2*lq + 1];
      }
      #pragma unroll
      for (int mt = 0; mt < 2; mt++){
        if (MASKED){
          sc[mt][nt][0] += (ck0 == rq[mt][0]) ? 0.f : -80.f;
          sc[mt][nt][1] += (ck1 == rq[mt][0]) ? 0.f : -80.f;
          sc[mt][nt][2] += (ck0 == rq[mt][1]) ? 0.f : -80.f;
          sc[mt][nt][3] += (ck1 == rq[mt][1]) ? 0.f : -80.f;
        }
        sc[mt][nt][0] = exp2m(sc[mt][nt][0]);
        sc[mt][nt][1] = exp2m(sc[mt][nt][1]);
        sc[mt][nt][2] = exp2m(sc[mt][nt][2]);
        sc[mt][nt][3] = exp2m(sc[mt][nt][3]);
      }
    }

    // ---- O += P @ [V|1] ----
    #pragma unroll
    for (int ktv = 0; ktv < 4; ktv++){
      unsigned aP[2][4];
      #pragma unroll
      for (int mt = 0; mt < 2; mt++){
        float v0 = __shfl_sync(0xffffffffu, sc[mt][ktv][0], src1);
        float v1 = __shfl_sync(0xffffffffu, sc[mt][ktv][1], src1);
        float w0 = __shfl_sync(0xffffffffu, sc[mt][ktv][2], src1);
        float w1 = __shfl_sync(0xffffffffu, sc[mt][ktv][3], src1);
        float x0 = __shfl_sync(0xffffffffu, sc[mt][ktv][0], src2);
        float x1 = __shfl_sync(0xffffffffu, sc[mt][ktv][1], src2);
        float y0 = __shfl_sync(0xffffffffu, sc[mt][ktv][2], src2);
        float y1 = __shfl_sync(0xffffffffu, sc[mt][ktv][3], src2);
        aP[mt][0] = cvt_tf32(oddc ? v1 : v0);
        aP[mt][1] = cvt_tf32(oddc ? w1 : w0);
        aP[mt][2] = cvt_tf32(oddc ? x1 : x0);
        aP[mt][3] = cvt_tf32(oddc ? y1 : y0);
      }
      #pragma unroll
      for (int ntv = 0; ntv < 3; ntv++){
        int vb = (kb + ktv*8 + lq) * 25 + ntv*8 + lr;
        unsigned b0 = __float_as_uint(Vs[vb]);
        unsigned b1 = __float_as_uint(Vs[vb + 4*25]);
        mma_tf32(oc[0][ntv], aP[0], b0, b1);
        mma_tf32(oc[1][ntv], aP[1], b0, b1);
      }
    }
  }

  // ---- epilogue: divide by rowsum (col 20 of O), scatter to global ----
  #pragma unroll
  for (int mt = 0; mt < 2; mt++){
    float ls0 = __shfl_sync(0xffffffffu, oc[mt][2][0], (lane & 28) | 2);
    float ls1 = __shfl_sync(0xffffffffu, oc[mt][2][2], (lane & 28) | 2);
    float inv0 = 1.0f / ls0;
    float inv1 = 1.0f / ls1;
    int r0 = m0w + mt*16 + lr;
    int g0 = gidxs[r0], g1 = gidxs[r0 + 8];
    float* o0 = out + (size_t)g0*60 + head*20;
    float* o1 = out + (size_t)g1*60 + head*20;
    #pragma unroll
    for (int nt = 0; nt < 3; nt++){
      int c = nt*8 + 2*lq;
      if (c < 20){
        *reinterpret_cast<float2*>(o0 + c) =
            make_float2(oc[mt][nt][0]*inv0, oc[mt][nt][1]*inv0);
        *reinterpret_cast<float2*>(o1 + c) =
            make_float2(oc[mt][nt][2]*inv1, oc[mt][nt][3]*inv1);
      }
    }
  }
}

// ---------------- last conv (60->12) fused with PixelShuffle(2) ------------
__global__ __launch_bounds__(256) void conv_out_kernel(
    const float* __restrict__ feat, const float* __restrict__ w,
    const float* __restrict__ b, float* __restrict__ out)
{
  int idx = blockIdx.x*256 + threadIdx.x;
  if (idx >= 2*3*256*256) return;
  int xq = idx & 255;
  int yq = (idx >> 8) & 255;
  int c  = (idx >> 16) % 3;
  int bq = idx / (3*65536);
  int co = c*4 + (yq & 1)*2 + (xq & 1);
  int hi = yq >> 1, wi = xq >> 1;
  float s = b[co];
  #pragma unroll
  for (int kh = 0; kh < 3; kh++){
    int hh = hi + kh - 1;
    if ((unsigned)hh > 127u) continue;
    #pragma unroll
    for (int kw = 0; kw < 3; kw++){
      int wwq = wi + kw - 1;
      if ((unsigned)wwq > 127u) continue;
      const float* fp = feat + (size_t)((bq*128 + hh)*128 + wwq)*60;
      const float* wp = w + ((size_t)co*60)*9 + kh*3 + kw;
      #pragma unroll
      for (int ci = 0; ci < 60; ci++)
        s = fmaf(fp[ci], wp[(size_t)ci*9], s);
    }
  }
  out[idx] = s;
}

// ---------------- launcher -------------------------------------------------
extern "C" void kernel_launch(void* const* d_in, const int* in_sizes, int n_in,
                              void* d_out, int out_size)
{
  const float* x      = (const float*)d_in[0];
  const float* conv_w = (const float*)d_in[1];
  const float* conv_b = (const float*)d_in[2];
  const float* ln1_g  = (const float*)d_in[3];
  const float* ln1_b  = (const float*)d_in[4];
  const float* qkv_w  = (const float*)d_in[5];
  const float* qkv_b  = (const float*)d_in[6];
  const float* proj_w = (const float*)d_in[7];
  const float* proj_b = (const float*)d_in[8];
  const float* ln2_g  = (const float*)d_in[9];
  const float* ln2_b  = (const float*)d_in[10];
  const float* fc1_w  = (const float*)d_in[11];
  const float* fc1_b  = (const float*)d_in[12];
  const float* fc2_w  = (const float*)d_in[13];
  const float* fc2_b  = (const float*)d_in[14];
  const float* last_w = (const float*)d_in[15];
  const float* last_b = (const float*)d_in[16];
  float* out = (float*)d_out;

  cudaFuncSetAttribute(fused_mlp_kernel,
                       cudaFuncAttributeMaxDynamicSharedMemorySize,
                       FMLP_SMEM_BYTES);
  cudaFuncSetAttribute(attn_kernel<0>,
                       cudaFuncAttributeMaxDynamicSharedMemorySize,
                       ATTN_SMEM_BYTES);
  cudaFuncSetAttribute(attn_kernel<1>,
                       cudaFuncAttributeMaxDynamicSharedMemorySize,
                       ATTN_SMEM_BYTES);

  float *feat, *qkvb, *attnb;
  cudaGetSymbolAddress((void**)&feat,  g_feat);
  cudaGetSymbolAddress((void**)&qkvb,  g_qkv);
  cudaGetSymbolAddress((void**)&attnb, g_attn);

  conv_in_kernel<<<(TOKENS*60 + 255)/256, 256>>>(x, conv_w, conv_b, feat);

  for (int l = 0; l < 36; l++){
    int i  = l % 6;
    int wi = i & 1;
    int wh = wi ? 8  : 32;
    int ww = wi ? 32 : 8;
    int shifted = (i % 4) >= 2;
    int sh = shifted ? (wi ? 4  : 16) : 0;
    int sw = shifted ? (wi ? 16 : 4 ) : 0;

    gemm_kernel<60,true,false><<<dim3(256,3), 240>>>(
        feat, qkv_w + (size_t)l*60*180, qkv_b + (size_t)l*180,
        ln1_g + (size_t)l*60, ln1_b + (size_t)l*60, qkvb, 180);

    if (shifted)
      attn_kernel<1><<<dim3(128,3), 256, ATTN_SMEM_BYTES>>>(qkvb, attnb, wh, ww, sh, sw);
    else
      attn_kernel<0><<<dim3(128,3), 256, ATTN_SMEM_BYTES>>>(qkvb, attnb, wh, ww, 0, 0);

    gemm_kernel<60,false,true><<<dim3(256,1), 240>>>(
        attnb, proj_w + (size_t)l*3600, proj_b + (size_t)l*60,
        nullptr, nullptr, feat, 60);

    fused_mlp_kernel<<<256, 240, FMLP_SMEM_BYTES>>>(
        feat, fc1_w + (size_t)l*7200, fc1_b + (size_t)l*120,
        fc2_w + (size_t)l*7200, fc2_b + (size_t)l*60,
        ln2_g + (size_t)l*60, ln2_b + (size_t)l*60);
  }

  conv_out_kernel<<<(2*3*256*256 + 255)/256, 256>>>(feat, last_w, last_b, out);
}